// round 13
// baseline (speedup 1.0000x reference)
#include <cuda_runtime.h>

#define DIM 1024
#define TPB 256          // thread t owns float4 column t of each 1024-float row
#define ROW_UNROLL 8     // 4096 blocks * 8 rows = 32768 rows, exact

__global__ __launch_bounds__(TPB) void fused_mask_mul_kernel(
    const float4* __restrict__ x4,
    const float4* __restrict__ mask_param4,
    const float4* __restrict__ mvec4,
    float4* __restrict__ out4,
    int nrows)                      // nrows = n / 1024
{
    const int t = threadIdx.x;
    __shared__ float red[8];        // 8 warps per block

    const size_t rowq = DIM / 4;
    size_t base = (size_t)blockIdx.x * ROW_UNROLL * rowq + t;
    const int row0 = blockIdx.x * ROW_UNROLL;
    const bool full_strip = (row0 + ROW_UNROLL <= nrows);

    // ---- issue the block's strip loads FIRST (independent of the mask) ----
    // 8 front-batched LDG.128 per thread; softmax latency hides under them.
    float4 v[ROW_UNROLL];
    if (full_strip) {
        #pragma unroll
        for (int r = 0; r < ROW_UNROLL; r++)
            v[r] = __ldcs(&x4[base + (size_t)r * rowq]);
    }

    // ---- softmax computed while the loads are in flight ----
    float4 p = mask_param4[t];

    float m = fmaxf(fmaxf(p.x, p.y), fmaxf(p.z, p.w));
    #pragma unroll
    for (int o = 16; o; o >>= 1) m = fmaxf(m, __shfl_xor_sync(0xFFFFFFFFu, m, o));
    if ((t & 31) == 0) red[t >> 5] = m;
    __syncthreads();
    float maxv = red[0];
    #pragma unroll
    for (int i = 1; i < 8; i++) maxv = fmaxf(maxv, red[i]);
    __syncthreads();

    float e0 = __expf(p.x - maxv);
    float e1 = __expf(p.y - maxv);
    float e2 = __expf(p.z - maxv);
    float e3 = __expf(p.w - maxv);

    float s = e0 + e1 + e2 + e3;
    #pragma unroll
    for (int o = 16; o; o >>= 1) s += __shfl_xor_sync(0xFFFFFFFFu, s, o);
    if ((t & 31) == 0) red[t >> 5] = s;
    __syncthreads();
    float sum = 0.f;
    #pragma unroll
    for (int i = 0; i < 8; i++) sum += red[i];

    float4 mv = mvec4[t];
    float inv = (float)DIM / sum;   // PRUNE_RATE = 1.0
    float4 mk;
    mk.x = e0 * inv * mv.x;
    mk.y = e1 * inv * mv.y;
    mk.z = e2 * inv * mv.z;
    mk.w = e3 * inv * mv.w;

    // mask tail: out[n .. n+1023], written once by block 0
    if (blockIdx.x == 0)
        out4[(size_t)nrows * rowq + t] = mk;

    // ---- multiply + store fused per row (store r waits only on load r);
    //      write-through stores keep L2 slots free for the read stream ----
    if (full_strip) {
        #pragma unroll
        for (int r = 0; r < ROW_UNROLL; r++) {
            v[r].x *= mk.x; v[r].y *= mk.y; v[r].z *= mk.z; v[r].w *= mk.w;
            __stwt(&out4[base + (size_t)r * rowq], v[r]);
        }
    } else {
        // partial strip at the end (bench shape divides evenly; safety path)
        for (int row = row0; row < nrows; row++, base += rowq) {
            float4 w = __ldcs(&x4[base]);
            w.x *= mk.x; w.y *= mk.y; w.z *= mk.z; w.w *= mk.w;
            __stwt(&out4[base], w);
        }
    }
}

extern "C" void kernel_launch(void* const* d_in, const int* in_sizes, int n_in,
                              void* d_out, int out_size) {
    const float* x          = (const float*)d_in[0];  // [8,4096,1024] fp32
    const float* mask_param = (const float*)d_in[1];  // [1024]
    const float* mvec       = (const float*)d_in[2];  // [1024]

    int n = in_sizes[0];
    int nrows = n / DIM;
    int blocks = (nrows + ROW_UNROLL - 1) / ROW_UNROLL;  // 4096 for bench shape

    fused_mask_mul_kernel<<<blocks, TPB>>>(
        (const float4*)x, (const float4*)mask_param, (const float4*)mvec,
        (float4*)d_out, nrows);
}

// round 14
// speedup vs baseline: 1.0307x; 1.0307x over previous
#include <cuda_runtime.h>

#define DIM 1024
#define TPB 256          // thread t owns float4 column t of each 1024-float row
#define ROW_UNROLL 8     // 4096 blocks * 8 rows = 32768 rows, exact

__global__ __launch_bounds__(TPB) void fused_mask_mul_kernel(
    const float4* __restrict__ x4,
    const float4* __restrict__ mask_param4,
    const float4* __restrict__ mvec4,
    float4* __restrict__ out4,
    int nrows)                      // nrows = n / 1024
{
    const int t = threadIdx.x;
    __shared__ float red[8];        // 8 warps per block

    const size_t rowq = DIM / 4;
    size_t base = (size_t)blockIdx.x * ROW_UNROLL * rowq + t;
    const int row0 = blockIdx.x * ROW_UNROLL;
    const bool full_strip = (row0 + ROW_UNROLL <= nrows);

    // ---- issue the block's strip loads FIRST (independent of the mask) ----
    // 8 front-batched LDG.128 per thread; softmax latency hides under them.
    float4 v[ROW_UNROLL];
    if (full_strip) {
        #pragma unroll
        for (int r = 0; r < ROW_UNROLL; r++)
            v[r] = __ldcs(&x4[base + (size_t)r * rowq]);
    }

    // ---- softmax computed while the loads are in flight ----
    float4 p = mask_param4[t];

    float m = fmaxf(fmaxf(p.x, p.y), fmaxf(p.z, p.w));
    #pragma unroll
    for (int o = 16; o; o >>= 1) m = fmaxf(m, __shfl_xor_sync(0xFFFFFFFFu, m, o));
    if ((t & 31) == 0) red[t >> 5] = m;
    __syncthreads();
    float maxv = red[0];
    #pragma unroll
    for (int i = 1; i < 8; i++) maxv = fmaxf(maxv, red[i]);
    __syncthreads();

    float e0 = __expf(p.x - maxv);
    float e1 = __expf(p.y - maxv);
    float e2 = __expf(p.z - maxv);
    float e3 = __expf(p.w - maxv);

    float s = e0 + e1 + e2 + e3;
    #pragma unroll
    for (int o = 16; o; o >>= 1) s += __shfl_xor_sync(0xFFFFFFFFu, s, o);
    if ((t & 31) == 0) red[t >> 5] = s;
    __syncthreads();
    float sum = 0.f;
    #pragma unroll
    for (int i = 0; i < 8; i++) sum += red[i];

    float4 mv = mvec4[t];
    float inv = (float)DIM / sum;   // PRUNE_RATE = 1.0
    float4 mk;
    mk.x = e0 * inv * mv.x;
    mk.y = e1 * inv * mv.y;
    mk.z = e2 * inv * mv.z;
    mk.w = e3 * inv * mv.w;

    // mask tail: out[n .. n+1023], written once by block 0
    if (blockIdx.x == 0)
        out4[(size_t)nrows * rowq + t] = mk;

    // ---- multiply + store fused per row: store r depends only on load r,
    //      so early stores issue while later loads are still in flight ----
    if (full_strip) {
        #pragma unroll
        for (int r = 0; r < ROW_UNROLL; r++) {
            v[r].x *= mk.x; v[r].y *= mk.y; v[r].z *= mk.z; v[r].w *= mk.w;
            __stcs(&out4[base + (size_t)r * rowq], v[r]);
        }
    } else {
        // partial strip at the end (bench shape divides evenly; safety path)
        for (int row = row0; row < nrows; row++, base += rowq) {
            float4 w = __ldcs(&x4[base]);
            w.x *= mk.x; w.y *= mk.y; w.z *= mk.z; w.w *= mk.w;
            __stcs(&out4[base], w);
        }
    }
}

extern "C" void kernel_launch(void* const* d_in, const int* in_sizes, int n_in,
                              void* d_out, int out_size) {
    const float* x          = (const float*)d_in[0];  // [8,4096,1024] fp32
    const float* mask_param = (const float*)d_in[1];  // [1024]
    const float* mvec       = (const float*)d_in[2];  // [1024]

    int n = in_sizes[0];
    int nrows = n / DIM;
    int blocks = (nrows + ROW_UNROLL - 1) / ROW_UNROLL;  // 4096 for bench shape

    fused_mask_mul_kernel<<<blocks, TPB>>>(
        (const float4*)x, (const float4*)mask_param, (const float4*)mvec,
        (float4*)d_out, nrows);
}

// round 15
// speedup vs baseline: 1.0368x; 1.0059x over previous
#include <cuda_runtime.h>

#define DIM 1024
#define TPB 128          // thread t owns 8 floats (32 B) of each 1024-float row
#define ROW_UNROLL 4     // 8192 blocks * 4 rows = 32768 rows, exact
                         // 4 x 32 B = 128 B front-batched per thread (matches R12)

__device__ __forceinline__ void ldg256_cs(const float* __restrict__ p, float v[8]) {
    asm volatile("ld.global.cs.v8.f32 {%0,%1,%2,%3,%4,%5,%6,%7}, [%8];"
        : "=f"(v[0]), "=f"(v[1]), "=f"(v[2]), "=f"(v[3]),
          "=f"(v[4]), "=f"(v[5]), "=f"(v[6]), "=f"(v[7])
        : "l"(p));
}
__device__ __forceinline__ void stg256_cs(float* __restrict__ p, const float v[8]) {
    asm volatile("st.global.cs.v8.f32 [%0], {%1,%2,%3,%4,%5,%6,%7,%8};"
        :: "l"(p),
           "f"(v[0]), "f"(v[1]), "f"(v[2]), "f"(v[3]),
           "f"(v[4]), "f"(v[5]), "f"(v[6]), "f"(v[7])
        : "memory");
}

__global__ __launch_bounds__(TPB) void fused_mask_mul_kernel(
    const float* __restrict__ x,
    const float4* __restrict__ mask_param4,
    const float4* __restrict__ mvec4,
    float* __restrict__ out,
    int nrows)                      // nrows = n / 1024
{
    const int t = threadIdx.x;
    __shared__ float red[4];        // 4 warps per block

    const size_t rowf = DIM;        // floats per row
    size_t basef = (size_t)blockIdx.x * ROW_UNROLL * rowf + (size_t)t * 8;
    const int row0 = blockIdx.x * ROW_UNROLL;
    const bool full_strip = (row0 + ROW_UNROLL <= nrows);

    // ---- issue the block's strip loads FIRST (256-bit, front-batched) ----
    float v[ROW_UNROLL][8];
    if (full_strip) {
        #pragma unroll
        for (int r = 0; r < ROW_UNROLL; r++)
            ldg256_cs(&x[basef + (size_t)r * rowf], v[r]);
    }

    // ---- softmax computed while the loads are in flight ----
    // thread t owns elements [8t, 8t+8) = float4 indices 2t, 2t+1
    float4 p0 = mask_param4[2 * t];
    float4 p1 = mask_param4[2 * t + 1];

    float m = fmaxf(fmaxf(fmaxf(p0.x, p0.y), fmaxf(p0.z, p0.w)),
                    fmaxf(fmaxf(p1.x, p1.y), fmaxf(p1.z, p1.w)));
    #pragma unroll
    for (int o = 16; o; o >>= 1) m = fmaxf(m, __shfl_xor_sync(0xFFFFFFFFu, m, o));
    if ((t & 31) == 0) red[t >> 5] = m;
    __syncthreads();
    float maxv = fmaxf(fmaxf(red[0], red[1]), fmaxf(red[2], red[3]));
    __syncthreads();

    float e[8];
    e[0] = __expf(p0.x - maxv); e[1] = __expf(p0.y - maxv);
    e[2] = __expf(p0.z - maxv); e[3] = __expf(p0.w - maxv);
    e[4] = __expf(p1.x - maxv); e[5] = __expf(p1.y - maxv);
    e[6] = __expf(p1.z - maxv); e[7] = __expf(p1.w - maxv);

    float s = ((e[0] + e[1]) + (e[2] + e[3])) + ((e[4] + e[5]) + (e[6] + e[7]));
    #pragma unroll
    for (int o = 16; o; o >>= 1) s += __shfl_xor_sync(0xFFFFFFFFu, s, o);
    if ((t & 31) == 0) red[t >> 5] = s;
    __syncthreads();
    float sum = (red[0] + red[1]) + (red[2] + red[3]);

    float4 mv0 = mvec4[2 * t];
    float4 mv1 = mvec4[2 * t + 1];
    float inv = (float)DIM / sum;   // PRUNE_RATE = 1.0
    float mk[8];
    mk[0] = e[0] * inv * mv0.x; mk[1] = e[1] * inv * mv0.y;
    mk[2] = e[2] * inv * mv0.z; mk[3] = e[3] * inv * mv0.w;
    mk[4] = e[4] * inv * mv1.x; mk[5] = e[5] * inv * mv1.y;
    mk[6] = e[6] * inv * mv1.z; mk[7] = e[7] * inv * mv1.w;

    // mask tail: out[n .. n+1023], written once by block 0
    if (blockIdx.x == 0) {
        float* tail = out + (size_t)nrows * rowf + (size_t)t * 8;
        #pragma unroll
        for (int i = 0; i < 8; i++) tail[i] = mk[i];
    }

    // ---- multiply + store fused per row (store r depends only on load r) ----
    if (full_strip) {
        #pragma unroll
        for (int r = 0; r < ROW_UNROLL; r++) {
            #pragma unroll
            for (int i = 0; i < 8; i++) v[r][i] *= mk[i];
            stg256_cs(&out[basef + (size_t)r * rowf], v[r]);
        }
    } else {
        // partial strip at the end (bench shape divides evenly; safety path)
        for (int row = row0; row < nrows; row++, basef += rowf) {
            float w[8];
            ldg256_cs(&x[basef], w);
            #pragma unroll
            for (int i = 0; i < 8; i++) w[i] *= mk[i];
            stg256_cs(&out[basef], w);
        }
    }
}

extern "C" void kernel_launch(void* const* d_in, const int* in_sizes, int n_in,
                              void* d_out, int out_size) {
    const float* x          = (const float*)d_in[0];  // [8,4096,1024] fp32
    const float* mask_param = (const float*)d_in[1];  // [1024]
    const float* mvec       = (const float*)d_in[2];  // [1024]

    int n = in_sizes[0];
    int nrows = n / DIM;
    int blocks = (nrows + ROW_UNROLL - 1) / ROW_UNROLL;  // 8192 for bench shape

    fused_mask_mul_kernel<<<blocks, TPB>>>(
        x, (const float4*)mask_param, (const float4*)mvec,
        (float*)d_out, nrows);
}